// round 15
// baseline (speedup 1.0000x reference)
#include <cuda_runtime.h>
#include <cuda_fp16.h>
#include <cstdint>

#define N_IMG 16
#define C_IN  256
#define HW    128
#define C_OUT 128
#define HALO  130

// Pre-transformed input: [n][halo_row 130][coord 4][tile 64][ci 256] f16.
// Zero-init => halo rows 0 and 129 stay zero (transform of zeros is zero).
__device__ __align__(1024) __half g_xV[(size_t)N_IMG * HALO * 4 * 64 * C_IN];
// Winograd-transformed weights, B-fragment order: [coord4][chunk12][kt4][nt16][lane32]
__device__ __align__(16) uint2 g_wfrag[4 * 12 * 4 * 16 * 32];
__device__ float g_alpha[C_OUT];

__device__ __forceinline__ float sgnf(float v) {
    return (v > 0.f) ? 1.f : ((v < 0.f) ? -1.f : 0.f);
}

// ---------------------------------------------------------------------------
// Kernel 1: sign(x) + Winograd F(2,3) input transform along w.
//   Block = (ct: 64 ci, T: 32-tile half, n*h). Loads the 66 halo pixels
//   covering tiles 32T..32T+31, computes v0=d0-d2, v1=d1+d2, v2=d2-d1,
//   v3=d1-d3 per tile, writes g_xV (halo row h+1). All values exact in f16.
// ---------------------------------------------------------------------------
__global__ void pack_x_kernel(const float* __restrict__ x) {
    __shared__ __half sm[66 * 72];    // [local px 0..65][ci 64, pad to 72]
    int nh = blockIdx.z;              // n*128 + h
    int n = nh >> 7, h = nh & 127;
    int T  = blockIdx.y;              // 0..1
    int ct = blockIdx.x;              // 0..3 (ci tile of 64)
    int tid = threadIdx.x;
    int lane = tid & 31, wp = tid >> 5;

#pragma unroll
    for (int r = 0; r < 8; r++) {
        int c = wp + r * 8;
        const float* xr = x + (((size_t)(n * C_IN + ct * 64 + c)) * HW + h) * HW;
#pragma unroll
        for (int k = 0; k < 3; k++) {
            int i = lane + k * 32;            // local halo px
            if (i < 66) {
                int w = T * 64 + i - 1;       // real w (halo px = w+1)
                float v = (w >= 0 && w < HW) ? xr[w] : 0.f;
                sm[i * 72 + c] = __float2half(sgnf(v));
            }
        }
    }
    __syncthreads();

    int t = tid >> 3, seg = tid & 7;          // local tile 0..31, 16B segment
    uint4 d0 = *(const uint4*)&sm[(2 * t + 0) * 72 + seg * 8];
    uint4 d1 = *(const uint4*)&sm[(2 * t + 1) * 72 + seg * 8];
    uint4 d2 = *(const uint4*)&sm[(2 * t + 2) * 72 + seg * 8];
    uint4 d3 = *(const uint4*)&sm[(2 * t + 3) * 72 + seg * 8];

    uint4 v[4];
    const uint32_t* p0 = (const uint32_t*)&d0;
    const uint32_t* p1 = (const uint32_t*)&d1;
    const uint32_t* p2 = (const uint32_t*)&d2;
    const uint32_t* p3 = (const uint32_t*)&d3;
#pragma unroll
    for (int r = 0; r < 4; r++) {
        __half2 h0 = *(const __half2*)&p0[r], h1 = *(const __half2*)&p1[r];
        __half2 h2 = *(const __half2*)&p2[r], h3 = *(const __half2*)&p3[r];
        __half2 v0 = __hsub2(h0, h2), v1 = __hadd2(h1, h2);
        __half2 v2 = __hsub2(h2, h1), v3 = __hsub2(h1, h3);
        ((uint32_t*)&v[0])[r] = *(const uint32_t*)&v0;
        ((uint32_t*)&v[1])[r] = *(const uint32_t*)&v1;
        ((uint32_t*)&v[2])[r] = *(const uint32_t*)&v2;
        ((uint32_t*)&v[3])[r] = *(const uint32_t*)&v3;
    }

    // g_xV index = (n*130+row)*65536 + coord*16384 + tile*256 + ci
    size_t base = ((size_t)(n * HALO) + h + 1) * 65536
                + (size_t)(T * 32 + t) * 256 + ct * 64 + seg * 8;
#pragma unroll
    for (int c = 0; c < 4; c++)
        *(uint4*)&g_xV[base + (size_t)c * 16384] = v[c];
}

// ---------------------------------------------------------------------------
// Kernel 2: sign(W) OIHW -> Winograd F(2,3) weight transform along kx,
//   packed in mma.m16n8k16 B-fragment order.
//   U0 = g0, U1 = (g0+g1+g2)/2, U2 = (g0-g1+g2)/2, U3 = g2  (g = sign(w))
// ---------------------------------------------------------------------------
__global__ void pack_w_kernel(const float* __restrict__ w) {
    int g = blockIdx.x * 256 + threadIdx.x;    // 98304 total
    int lane = g & 31;
    int nt   = (g >> 5) & 15;
    int kt   = (g >> 9) & 3;
    int idx  = g >> 11;                        // 0..47 = c*12 + chunk
    int c = idx / 12, chunk = idx % 12;
    int ky = chunk >> 2, cc = chunk & 3;

    int ci0 = cc * 64 + kt * 16 + (lane & 3) * 2;
    int co  = nt * 8 + (lane >> 2);

    uint32_t bits[4];
    int cis[4] = {ci0, ci0 + 1, ci0 + 8, ci0 + 9};
#pragma unroll
    for (int j = 0; j < 4; j++) {
        const float* wp = w + ((size_t)(co * C_IN + cis[j]) * 3 + ky) * 3;
        float g0 = sgnf(wp[0]), g1 = sgnf(wp[1]), g2 = sgnf(wp[2]);
        float u = (c == 0) ? g0
                : (c == 1) ? 0.5f * (g0 + g1 + g2)
                : (c == 2) ? 0.5f * (g0 - g1 + g2)
                :            g2;
        __half hu = __float2half(u);
        bits[j] = (uint32_t)*reinterpret_cast<uint16_t*>(&hu);
    }
    g_wfrag[g] = make_uint2(bits[0] | (bits[1] << 16), bits[2] | (bits[3] << 16));
}

// ---------------------------------------------------------------------------
// Kernel 3: alpha[co] = mean |W[co,:,:,:]|
// ---------------------------------------------------------------------------
__global__ void alpha_kernel(const float* __restrict__ w) {
    __shared__ float red[256];
    int co = blockIdx.x;
    float s = 0.f;
    for (int i = threadIdx.x; i < 2304; i += 256)
        s += fabsf(w[(size_t)co * 2304 + i]);
    red[threadIdx.x] = s;
    __syncthreads();
    for (int o = 128; o > 0; o >>= 1) {
        if (threadIdx.x < o) red[threadIdx.x] += red[threadIdx.x + o];
        __syncthreads();
    }
    if (threadIdx.x == 0) g_alpha[co] = red[0] / 2304.f;
}

// ---------------------------------------------------------------------------
// Kernel 4: Winograd conv, V loaded PRE-TRANSFORMED from gmem (no in-loop
//   transform at all). 8 warps = (coord c, N-half n2), 64x64 warp tiles,
//   3-stage V ring via cp.async, B double-buffered in registers, 2 CTAs/SM.
// ---------------------------------------------------------------------------
#define A_PAD 72                          // halves; 144B row stride
#define VSTG (4 * 64 * 144)               // 36864 per stage
#define SMEM_DYN (3 * VSTG)               // 110592 (x2 CTAs = 221184 <= 228KB)

__device__ __forceinline__ void issue_V(char* smem, int tid, int n, int h, int s) {
    int ky = s >> 2, cc = s & 3;
    char* sV = smem + (s % 3) * VSTG;
    const __half* src = g_xV + ((size_t)(n * HALO) + h + ky) * 65536 + cc * 64;
#pragma unroll
    for (int v = 0; v < 8; v++) {
        int u = tid + v * 256;            // 2048 units of 16B
        int ctile = u >> 3, seg = u & 7;  // (coord*64+tile), 16B seg
        uint32_t sa = (uint32_t)__cvta_generic_to_shared(sV + ctile * 144 + seg * 16);
        const void* ga = src + (size_t)ctile * 256 + seg * 8;
        asm volatile("cp.async.cg.shared.global [%0], [%1], 16;\n" :: "r"(sa), "l"(ga));
    }
    asm volatile("cp.async.commit_group;\n");
}

__global__ void __launch_bounds__(256, 2) conv_kernel(float* __restrict__ out) {
    extern __shared__ char smem[];
    int tid = threadIdx.x;
    int lane = tid & 31, wid = tid >> 5;
    int c  = wid >> 1;        // coord 0..3
    int n2 = wid & 1;         // N-half 0..1 (64 couts)
    int h = blockIdx.x, n = blockIdx.y;

    uint32_t acc[4][8][2];    // f16x2 accumulators [mtile][ntile]
#pragma unroll
    for (int a = 0; a < 4; a++)
#pragma unroll
        for (int b = 0; b < 8; b++) { acc[a][b][0] = 0u; acc[a][b][1] = 0u; }

    // Double-buffered B fragments (per kt). Preload chunk 0, kt 0.
    uint2 bfr[2][8];
#pragma unroll
    for (int nt = 0; nt < 8; nt++)
        bfr[0][nt] = g_wfrag[(((size_t)(c * 12 + 0) * 4 + 0) * 16 + n2 * 8 + nt) * 32 + lane];

    issue_V(smem, tid, n, h, 0);
    issue_V(smem, tid, n, h, 1);

    int rl  = lane & 15;
    int cl2 = (lane >> 4) * 8;

    for (int s = 0; s < 12; s++) {
        // Complete V(s); keep V(s+1) in flight.
        if (s < 11) asm volatile("cp.async.wait_group 1;\n");
        else        asm volatile("cp.async.wait_group 0;\n");
        __syncthreads();
        // Slot (s+2)%3 held V(s-1), consumed at iter s-1 (all warps passed
        // this barrier) -> safe to overwrite.
        if (s + 2 < 12) issue_V(smem, tid, n, h, s + 2);

        const char* sVc = smem + (s % 3) * VSTG + c * (64 * 144);
#pragma unroll
        for (int kt = 0; kt < 4; kt++) {
            int cur = kt & 1, nxt = cur ^ 1;
            // Prefetch next kt's B (or next chunk's kt0) into the other buffer.
            if (!(s == 11 && kt == 3)) {
                int s2  = (kt < 3) ? s : s + 1;
                int kt2 = (kt < 3) ? kt + 1 : 0;
                const uint2* gBn = g_wfrag
                    + (((size_t)(c * 12 + s2) * 4 + kt2) * 16 + n2 * 8) * 32 + lane;
#pragma unroll
                for (int nt = 0; nt < 8; nt++)
                    bfr[nxt][nt] = gBn[nt * 32];
            }

            uint32_t a[4][4];
#pragma unroll
            for (int mt = 0; mt < 4; mt++) {
                uint32_t addr = (uint32_t)__cvta_generic_to_shared(
                    sVc + ((mt * 16 + rl) * A_PAD + kt * 16 + cl2) * 2);
                asm volatile(
                    "ldmatrix.sync.aligned.m8n8.x4.shared.b16 {%0,%1,%2,%3}, [%4];"
                    : "=r"(a[mt][0]), "=r"(a[mt][1]), "=r"(a[mt][2]), "=r"(a[mt][3])
                    : "r"(addr));
            }
#pragma unroll
            for (int mt = 0; mt < 4; mt++)
#pragma unroll
                for (int nt = 0; nt < 8; nt++)
                    asm volatile(
                        "mma.sync.aligned.m16n8k16.row.col.f16.f16.f16.f16 "
                        "{%0,%1}, {%2,%3,%4,%5}, {%6,%7}, {%0,%1};"
                        : "+r"(acc[mt][nt][0]), "+r"(acc[mt][nt][1])
                        : "r"(a[mt][0]), "r"(a[mt][1]), "r"(a[mt][2]), "r"(a[mt][3]),
                          "r"(bfr[cur][nt].x), "r"(bfr[cur][nt].y));
        }
    }

    // ---- Epilogue: inverse transform y0=M0+M1+M2, y1=M1-M2-M3, * alpha[w] ----
    __syncthreads();
    __half* Vr = (__half*)smem;     // [coord4][tile64][co 132-pad], reuses ring
#pragma unroll
    for (int mt = 0; mt < 4; mt++) {
        int r1 = mt * 16 + (lane >> 2);      // tile index
#pragma unroll
        for (int nt = 0; nt < 8; nt++) {
            int co0 = n2 * 64 + nt * 8 + (lane & 3) * 2;
            *(uint32_t*)&Vr[((size_t)(c * 64 + r1) * 132) + co0]     = acc[mt][nt][0];
            *(uint32_t*)&Vr[((size_t)(c * 64 + r1 + 8) * 132) + co0] = acc[mt][nt][1];
        }
    }
    __syncthreads();

    float al[4];
#pragma unroll
    for (int k = 0; k < 4; k++) al[k] = g_alpha[lane + k * 32];

#pragma unroll
    for (int q = 0; q < 16; q++) {
        int co = wid * 16 + q;
        float* ob = out + (((size_t)n * C_OUT + co) * HW + h) * HW;
#pragma unroll
        for (int k = 0; k < 4; k++) {
            int w = lane + k * 32;
            int t = w >> 1, p = w & 1;
            float m0 = __half2float(Vr[(size_t)(0 * 64 + t) * 132 + co]);
            float m1 = __half2float(Vr[(size_t)(1 * 64 + t) * 132 + co]);
            float m2 = __half2float(Vr[(size_t)(2 * 64 + t) * 132 + co]);
            float m3 = __half2float(Vr[(size_t)(3 * 64 + t) * 132 + co]);
            float y = p ? (m1 - m2 - m3) : (m0 + m1 + m2);
            ob[w] = y * al[k];
        }
    }
}

// ---------------------------------------------------------------------------
extern "C" void kernel_launch(void* const* d_in, const int* in_sizes, int n_in,
                              void* d_out, int out_size) {
    (void)in_sizes; (void)n_in; (void)out_size;
    const float* x = (const float*)d_in[0];
    const float* w = (const float*)d_in[1];
    float* out = (float*)d_out;

    cudaFuncSetAttribute(conv_kernel,
                         cudaFuncAttributeMaxDynamicSharedMemorySize, SMEM_DYN);

    pack_x_kernel<<<dim3(4, 2, N_IMG * HW), 256>>>(x);
    pack_w_kernel<<<384, 256>>>(w);
    alpha_kernel<<<C_OUT, 256>>>(w);
    conv_kernel<<<dim3(HW, N_IMG), 256, SMEM_DYN>>>(out);
}

// round 16
// speedup vs baseline: 1.1297x; 1.1297x over previous
#include <cuda_runtime.h>
#include <cuda_fp16.h>
#include <cstdint>

#define N_IMG 16
#define C_IN  256
#define HW    128
#define C_OUT 128
#define HALO  130

// Scratch (module-load allocated; zero-initialized => halo stays zero forever)
__device__ __align__(1024) __half g_xb[(size_t)N_IMG * HALO * HALO * C_IN];
// Winograd-transformed weights, B-fragment order: [coord4][chunk12][kt4][nt16][lane32]
__device__ __align__(16) uint2 g_wfrag[4 * 12 * 4 * 16 * 32];
__device__ float g_alpha[C_OUT];

__device__ __forceinline__ float sgnf(float v) {
    return (v > 0.f) ? 1.f : ((v < 0.f) ? -1.f : 0.f);
}

// ---------------------------------------------------------------------------
// Kernel 1: sign(x) NCHW f32 -> NHWC f16 with +1 halo offset (zero padding)
//   x reads are streaming (__ldcs): read-once, keep L2 for g_xb.
// ---------------------------------------------------------------------------
__global__ void pack_x_kernel(const float* __restrict__ x) {
    __shared__ float tile[64][33];
    int nh = blockIdx.z;              // n*128 + h
    int n = nh >> 7, h = nh & 127;
    int wt = blockIdx.y;              // 0..3  (w tile of 32)
    int ct = blockIdx.x;              // 0..3  (c tile of 64)
    int tx = threadIdx.x, ty = threadIdx.y;

#pragma unroll
    for (int j = 0; j < 8; j++) {
        int cl = ty + j * 8;          // 0..63
        float v = __ldcs(&x[(((size_t)(n * C_IN + ct * 64 + cl)) * HW + h) * HW
                            + wt * 32 + tx]);
        tile[cl][tx] = sgnf(v);
    }
    __syncthreads();
#pragma unroll
    for (int j = 0; j < 4; j++) {
        int wl = ty + j * 8;          // 0..31
        __half2 hv = __floats2half2_rn(tile[tx * 2][wl], tile[tx * 2 + 1][wl]);
        size_t dsth2 = ((((size_t)n * HALO + (h + 1)) * HALO + (wt * 32 + wl + 1)) * C_IN
                        + ct * 64) >> 1;
        reinterpret_cast<__half2*>(g_xb)[dsth2 + tx] = hv;
    }
}

// ---------------------------------------------------------------------------
// Kernel 2 (fused): blocks 0..383 = Winograd F(2,3) weight transform into
//   mma.m16n8k16 B-fragment order; blocks 384..511 = alpha reduction.
//   U0 = g0, U1 = (g0+g1+g2)/2, U2 = (g0-g1+g2)/2, U3 = g2  (g = sign(w))
// ---------------------------------------------------------------------------
__global__ void pack_w_alpha_kernel(const float* __restrict__ w) {
    if (blockIdx.x < 384) {
        int g = blockIdx.x * 256 + threadIdx.x;    // 98304 total
        int lane = g & 31;
        int nt   = (g >> 5) & 15;
        int kt   = (g >> 9) & 3;
        int idx  = g >> 11;                        // 0..47 = c*12 + chunk
        int c = idx / 12, chunk = idx % 12;
        int ky = chunk >> 2, cc = chunk & 3;

        int ci0 = cc * 64 + kt * 16 + (lane & 3) * 2;
        int co  = nt * 8 + (lane >> 2);

        uint32_t bits[4];
        int cis[4] = {ci0, ci0 + 1, ci0 + 8, ci0 + 9};
#pragma unroll
        for (int j = 0; j < 4; j++) {
            const float* wp = w + ((size_t)(co * C_IN + cis[j]) * 3 + ky) * 3;
            float g0 = sgnf(wp[0]), g1 = sgnf(wp[1]), g2 = sgnf(wp[2]);
            float u = (c == 0) ? g0
                    : (c == 1) ? 0.5f * (g0 + g1 + g2)
                    : (c == 2) ? 0.5f * (g0 - g1 + g2)
                    :            g2;
            __half hu = __float2half(u);
            bits[j] = (uint32_t)*reinterpret_cast<uint16_t*>(&hu);
        }
        g_wfrag[g] = make_uint2(bits[0] | (bits[1] << 16), bits[2] | (bits[3] << 16));
    } else {
        __shared__ float red[256];
        int co = blockIdx.x - 384;
        float s = 0.f;
        for (int i = threadIdx.x; i < 2304; i += 256)
            s += fabsf(w[(size_t)co * 2304 + i]);
        red[threadIdx.x] = s;
        __syncthreads();
        for (int o = 128; o > 0; o >>= 1) {
            if (threadIdx.x < o) red[threadIdx.x] += red[threadIdx.x + o];
            __syncthreads();
        }
        if (threadIdx.x == 0) g_alpha[co] = red[0] / 2304.f;
    }
}

// ---------------------------------------------------------------------------
// Kernel 3: Winograd-F(2,3)-along-w conv, 8 warps, 64x64 warp tiles, 2 CTA/SM.
//   (R12 structure, proven 301us.) Output stores streaming (__stcs).
// ---------------------------------------------------------------------------
#define A_PAD 72                          // halves; 144B row stride
#define A_ROWS 130
#define RAWSZ (A_ROWS * A_PAD * 2)        // 18720
#define VCOORD_SZ (64 * A_PAD * 2)        // 9216 bytes
#define VBUF_SZ (4 * VCOORD_SZ)           // 36864
#define V_OFF (2 * RAWSZ)                 // 37440
#define SMEM_DYN (V_OFF + 2 * VBUF_SZ)    // 111168 (x2 CTAs = 222336 <= 228KB)

__device__ __forceinline__ void issue_raw(char* smem, int tid, int n, int h, int s) {
    int ky = s >> 2, cc = s & 3;
    char* sR = smem + (s & 1) * RAWSZ;
    const __half* gx = &g_xb[(((size_t)n * HALO + h + ky) * HALO) * C_IN + cc * 64];
#pragma unroll
    for (int v = 0; v < 5; v++) {
        int u = tid + v * 256;            // 1040 units of 16B (130 rows x 8)
        if (u < A_ROWS * 8) {
            int row = u >> 3, seg = u & 7;
            uint32_t sa = (uint32_t)__cvta_generic_to_shared(sR + row * 144 + seg * 16);
            const void* ga = gx + (size_t)row * C_IN + seg * 8;
            asm volatile("cp.async.cg.shared.global [%0], [%1], 16;\n" :: "r"(sa), "l"(ga));
        }
    }
    asm volatile("cp.async.commit_group;\n");
}

// Part p (0..7) of the w-transform of chunk s: 2048 items = 64 tiles x 32 ci-h2;
// raw[s&1] (130px x 64ci) -> V[s&1] (4 coords x 64 tiles x 64ci)
__device__ __forceinline__ void transform_p(char* smem, int tid, int s, int p) {
    const __half2* sR = (const __half2*)(smem + (s & 1) * RAWSZ);  // 36 h2 per row
    __half2* pv = (__half2*)(smem + V_OFF + (s & 1) * VBUF_SZ);    // 36 h2 per tile-row
    int idx = p * 256 + tid;
    int t = idx >> 5, l = idx & 31;
    __half2 d0 = sR[(2 * t + 0) * 36 + l];
    __half2 d1 = sR[(2 * t + 1) * 36 + l];
    __half2 d2 = sR[(2 * t + 2) * 36 + l];
    __half2 d3 = sR[(2 * t + 3) * 36 + l];
    pv[0 * 2304 + t * 36 + l] = __hsub2(d0, d2);
    pv[1 * 2304 + t * 36 + l] = __hadd2(d1, d2);
    pv[2 * 2304 + t * 36 + l] = __hsub2(d2, d1);
    pv[3 * 2304 + t * 36 + l] = __hsub2(d1, d3);
}

__global__ void __launch_bounds__(256, 2) conv_kernel(float* __restrict__ out) {
    extern __shared__ char smem[];
    int tid = threadIdx.x;
    int lane = tid & 31, wid = tid >> 5;
    int c  = wid >> 1;        // coord 0..3
    int n2 = wid & 1;         // N-half 0..1 (64 couts)
    int h = blockIdx.x, n = blockIdx.y;

    uint32_t acc[4][8][2];    // f16x2 accumulators [mtile][ntile]
#pragma unroll
    for (int a = 0; a < 4; a++)
#pragma unroll
        for (int b = 0; b < 8; b++) { acc[a][b][0] = 0u; acc[a][b][1] = 0u; }

    // Double-buffered B fragments (per kt). Preload chunk 0, kt 0.
    uint2 bfr[2][8];
#pragma unroll
    for (int nt = 0; nt < 8; nt++)
        bfr[0][nt] = g_wfrag[(((size_t)(c * 12 + 0) * 4 + 0) * 16 + n2 * 8 + nt) * 32 + lane];

    // Prologue: raw0+raw1 in flight; transform chunk 0 fully.
    issue_raw(smem, tid, n, h, 0);
    issue_raw(smem, tid, n, h, 1);
    asm volatile("cp.async.wait_group 1;\n");   // raw0 complete
    __syncthreads();
#pragma unroll
    for (int p = 0; p < 8; p++) transform_p(smem, tid, 0, p);

    int rl  = lane & 15;
    int cl2 = (lane >> 4) * 8;

    for (int s = 0; s < 12; s++) {
        // wait raw(s+1) -> transform(s+1) may read it; barrier publishes
        // transform(s) (V[s&1]) to all warps.
        asm volatile("cp.async.wait_group 0;\n");
        __syncthreads();

        // Slot s&1 held raw(s), consumed by transform(s) last chunk -> reuse.
        if (s + 2 < 12) issue_raw(smem, tid, n, h, s + 2);

        const char* sVc = smem + V_OFF + (s & 1) * VBUF_SZ + c * VCOORD_SZ;
#pragma unroll
        for (int kt = 0; kt < 4; kt++) {
            int cur = kt & 1, nxt = cur ^ 1;
            // Prefetch next kt's B (or next chunk's kt0) into the other buffer.
            if (!(s == 11 && kt == 3)) {
                int s2  = (kt < 3) ? s : s + 1;
                int kt2 = (kt < 3) ? kt + 1 : 0;
                const uint2* gBn = g_wfrag
                    + (((size_t)(c * 12 + s2) * 4 + kt2) * 16 + n2 * 8) * 32 + lane;
#pragma unroll
                for (int nt = 0; nt < 8; nt++)
                    bfr[nxt][nt] = gBn[nt * 32];
            }

            uint32_t a[4][4];
#pragma unroll
            for (int mt = 0; mt < 4; mt++) {
                uint32_t addr = (uint32_t)__cvta_generic_to_shared(
                    sVc + ((mt * 16 + rl) * A_PAD + kt * 16 + cl2) * 2);
                asm volatile(
                    "ldmatrix.sync.aligned.m8n8.x4.shared.b16 {%0,%1,%2,%3}, [%4];"
                    : "=r"(a[mt][0]), "=r"(a[mt][1]), "=r"(a[mt][2]), "=r"(a[mt][3])
                    : "r"(addr));
            }
#pragma unroll
            for (int mt = 0; mt < 4; mt++)
#pragma unroll
                for (int nt = 0; nt < 8; nt++)
                    asm volatile(
                        "mma.sync.aligned.m16n8k16.row.col.f16.f16.f16.f16 "
                        "{%0,%1}, {%2,%3,%4,%5}, {%6,%7}, {%0,%1};"
                        : "+r"(acc[mt][nt][0]), "+r"(acc[mt][nt][1])
                        : "r"(a[mt][0]), "r"(a[mt][1]), "r"(a[mt][2]), "r"(a[mt][3]),
                          "r"(bfr[cur][nt].x), "r"(bfr[cur][nt].y));

            // Two transform parts for chunk s+1 (writes V[(s+1)&1], disjoint
            // from this chunk's V[s&1] reads -> drains under the MMA stream).
            if (s < 11) {
                transform_p(smem, tid, s + 1, 2 * kt);
                transform_p(smem, tid, s + 1, 2 * kt + 1);
            }
        }
    }

    // ---- Epilogue: inverse transform y0=M0+M1+M2, y1=M1-M2-M3, * alpha[w] ----
    __syncthreads();
    __half* Vr = (__half*)(smem + V_OFF);    // [coord4][tile64][co 132-pad]
#pragma unroll
    for (int mt = 0; mt < 4; mt++) {
        int r1 = mt * 16 + (lane >> 2);      // tile index
#pragma unroll
        for (int nt = 0; nt < 8; nt++) {
            int co0 = n2 * 64 + nt * 8 + (lane & 3) * 2;
            *(uint32_t*)&Vr[((size_t)(c * 64 + r1) * 132) + co0]     = acc[mt][nt][0];
            *(uint32_t*)&Vr[((size_t)(c * 64 + r1 + 8) * 132) + co0] = acc[mt][nt][1];
        }
    }
    __syncthreads();

    float al[4];
#pragma unroll
    for (int k = 0; k < 4; k++) al[k] = g_alpha[lane + k * 32];

#pragma unroll
    for (int q = 0; q < 16; q++) {
        int co = wid * 16 + q;
        float* ob = out + (((size_t)n * C_OUT + co) * HW + h) * HW;
#pragma unroll
        for (int k = 0; k < 4; k++) {
            int w = lane + k * 32;
            int t = w >> 1, p = w & 1;
            float m0 = __half2float(Vr[(size_t)(0 * 64 + t) * 132 + co]);
            float m1 = __half2float(Vr[(size_t)(1 * 64 + t) * 132 + co]);
            float m2 = __half2float(Vr[(size_t)(2 * 64 + t) * 132 + co]);
            float m3 = __half2float(Vr[(size_t)(3 * 64 + t) * 132 + co]);
            float y = p ? (m1 - m2 - m3) : (m0 + m1 + m2);
            __stcs(&ob[w], y * al[k]);       // streaming: out never re-read
        }
    }
}

// ---------------------------------------------------------------------------
extern "C" void kernel_launch(void* const* d_in, const int* in_sizes, int n_in,
                              void* d_out, int out_size) {
    (void)in_sizes; (void)n_in; (void)out_size;
    const float* x = (const float*)d_in[0];
    const float* w = (const float*)d_in[1];
    float* out = (float*)d_out;

    cudaFuncSetAttribute(conv_kernel,
                         cudaFuncAttributeMaxDynamicSharedMemorySize, SMEM_DYN);

    dim3 pg(4, 4, N_IMG * HW);
    dim3 pb(32, 8);
    pack_x_kernel<<<pg, pb>>>(x);
    pack_w_alpha_kernel<<<512, 256>>>(w);
    conv_kernel<<<dim3(HW, N_IMG), 256, SMEM_DYN>>>(out);
}

// round 17
// speedup vs baseline: 1.1365x; 1.0060x over previous
#include <cuda_runtime.h>
#include <cuda_fp16.h>
#include <cstdint>

#define N_IMG 16
#define C_IN  256
#define HW    128
#define C_OUT 128
#define HALO  130

// Scratch (module-load allocated; zero-initialized => halo stays zero forever)
__device__ __align__(1024) __half g_xb[(size_t)N_IMG * HALO * HALO * C_IN];
// Winograd-transformed weights, B-fragment order: [coord4][chunk12][kt4][nt16][lane32]
__device__ __align__(16) uint2 g_wfrag[4 * 12 * 4 * 16 * 32];
__device__ float g_alpha[C_OUT];

__device__ __forceinline__ float sgnf(float v) {
    return (v > 0.f) ? 1.f : ((v < 0.f) ? -1.f : 0.f);
}

// ---------------------------------------------------------------------------
// Kernel 1: sign(x) NCHW f32 -> NHWC f16 with +1 halo offset (zero padding).
//   32-bit addressing, loop-invariant bases + additive strides (alu relief).
// ---------------------------------------------------------------------------
__global__ void pack_x_kernel(const float* __restrict__ x) {
    __shared__ float tile[64][33];
    int nh = blockIdx.z;              // n*128 + h
    int n = nh >> 7, h = nh & 127;
    int wt = blockIdx.y;              // 0..3  (w tile of 32)
    int ct = blockIdx.x;              // 0..3  (c tile of 64)
    int tx = threadIdx.x, ty = threadIdx.y;

    // ---- load 64c x 32w, sign, transpose-stage in smem ----
    const float* xp = x + ((unsigned)(n * C_IN + ct * 64 + ty) * HW + (unsigned)h) * HW
                        + wt * 32 + tx;
    const unsigned xstep = 8u * HW * HW;
#pragma unroll
    for (int j = 0; j < 8; j++) {
        tile[ty + j * 8][tx] = sgnf(__ldcs(xp));
        xp += xstep;
    }
    __syncthreads();

    // ---- store NHWC half2, additive dst stride ----
    __half2* gp = reinterpret_cast<__half2*>(g_xb);
    unsigned d2 = (((unsigned)(n * HALO + h + 1) * HALO + wt * 32 + ty + 1) * C_IN
                   + ct * 64) >> 1;
    d2 += tx;
    const unsigned dstep = 8u * C_IN / 2;
#pragma unroll
    for (int j = 0; j < 4; j++) {
        int wl = ty + j * 8;
        gp[d2] = __floats2half2_rn(tile[tx * 2][wl], tile[tx * 2 + 1][wl]);
        d2 += dstep;
    }
}

// ---------------------------------------------------------------------------
// Kernel 2 (fused): blocks 0..383 = Winograd F(2,3) weight transform into
//   mma.m16n8k16 B-fragment order; blocks 384..511 = alpha reduction.
//   U0 = g0, U1 = (g0+g1+g2)/2, U2 = (g0-g1+g2)/2, U3 = g2  (g = sign(w))
// ---------------------------------------------------------------------------
__global__ void pack_w_alpha_kernel(const float* __restrict__ w) {
    if (blockIdx.x < 384) {
        int g = blockIdx.x * 256 + threadIdx.x;    // 98304 total
        int lane = g & 31;
        int nt   = (g >> 5) & 15;
        int kt   = (g >> 9) & 3;
        int idx  = g >> 11;                        // 0..47 = c*12 + chunk
        int c = idx / 12, chunk = idx % 12;
        int ky = chunk >> 2, cc = chunk & 3;

        int ci0 = cc * 64 + kt * 16 + (lane & 3) * 2;
        int co  = nt * 8 + (lane >> 2);

        uint32_t bits[4];
        int cis[4] = {ci0, ci0 + 1, ci0 + 8, ci0 + 9};
#pragma unroll
        for (int j = 0; j < 4; j++) {
            const float* wp = w + ((size_t)(co * C_IN + cis[j]) * 3 + ky) * 3;
            float g0 = sgnf(wp[0]), g1 = sgnf(wp[1]), g2 = sgnf(wp[2]);
            float u = (c == 0) ? g0
                    : (c == 1) ? 0.5f * (g0 + g1 + g2)
                    : (c == 2) ? 0.5f * (g0 - g1 + g2)
                    :            g2;
            __half hu = __float2half(u);
            bits[j] = (uint32_t)*reinterpret_cast<uint16_t*>(&hu);
        }
        g_wfrag[g] = make_uint2(bits[0] | (bits[1] << 16), bits[2] | (bits[3] << 16));
    } else {
        __shared__ float red[256];
        int co = blockIdx.x - 384;
        float s = 0.f;
        for (int i = threadIdx.x; i < 2304; i += 256)
            s += fabsf(w[(size_t)co * 2304 + i]);
        red[threadIdx.x] = s;
        __syncthreads();
        for (int o = 128; o > 0; o >>= 1) {
            if (threadIdx.x < o) red[threadIdx.x] += red[threadIdx.x + o];
            __syncthreads();
        }
        if (threadIdx.x == 0) g_alpha[co] = red[0] / 2304.f;
    }
}

// ---------------------------------------------------------------------------
// Kernel 3: Winograd-F(2,3)-along-w conv, 8 warps, 64x64 warp tiles, 2 CTA/SM.
//   (R12/R16 structure, proven 301us.) Output stores streaming (__stcs).
// ---------------------------------------------------------------------------
#define A_PAD 72                          // halves; 144B row stride
#define A_ROWS 130
#define RAWSZ (A_ROWS * A_PAD * 2)        // 18720
#define VCOORD_SZ (64 * A_PAD * 2)        // 9216 bytes
#define VBUF_SZ (4 * VCOORD_SZ)           // 36864
#define V_OFF (2 * RAWSZ)                 // 37440
#define SMEM_DYN (V_OFF + 2 * VBUF_SZ)    // 111168 (x2 CTAs = 222336 <= 228KB)

__device__ __forceinline__ void issue_raw(char* smem, int tid, int n, int h, int s) {
    int ky = s >> 2, cc = s & 3;
    char* sR = smem + (s & 1) * RAWSZ;
    const __half* gx = &g_xb[(((size_t)n * HALO + h + ky) * HALO) * C_IN + cc * 64];
#pragma unroll
    for (int v = 0; v < 5; v++) {
        int u = tid + v * 256;            // 1040 units of 16B (130 rows x 8)
        if (u < A_ROWS * 8) {
            int row = u >> 3, seg = u & 7;
            uint32_t sa = (uint32_t)__cvta_generic_to_shared(sR + row * 144 + seg * 16);
            const void* ga = gx + (size_t)row * C_IN + seg * 8;
            asm volatile("cp.async.cg.shared.global [%0], [%1], 16;\n" :: "r"(sa), "l"(ga));
        }
    }
    asm volatile("cp.async.commit_group;\n");
}

// Part p (0..7) of the w-transform of chunk s: 2048 items = 64 tiles x 32 ci-h2;
// raw[s&1] (130px x 64ci) -> V[s&1] (4 coords x 64 tiles x 64ci)
__device__ __forceinline__ void transform_p(char* smem, int tid, int s, int p) {
    const __half2* sR = (const __half2*)(smem + (s & 1) * RAWSZ);  // 36 h2 per row
    __half2* pv = (__half2*)(smem + V_OFF + (s & 1) * VBUF_SZ);    // 36 h2 per tile-row
    int idx = p * 256 + tid;
    int t = idx >> 5, l = idx & 31;
    __half2 d0 = sR[(2 * t + 0) * 36 + l];
    __half2 d1 = sR[(2 * t + 1) * 36 + l];
    __half2 d2 = sR[(2 * t + 2) * 36 + l];
    __half2 d3 = sR[(2 * t + 3) * 36 + l];
    pv[0 * 2304 + t * 36 + l] = __hsub2(d0, d2);
    pv[1 * 2304 + t * 36 + l] = __hadd2(d1, d2);
    pv[2 * 2304 + t * 36 + l] = __hsub2(d2, d1);
    pv[3 * 2304 + t * 36 + l] = __hsub2(d1, d3);
}

__global__ void __launch_bounds__(256, 2) conv_kernel(float* __restrict__ out) {
    extern __shared__ char smem[];
    int tid = threadIdx.x;
    int lane = tid & 31, wid = tid >> 5;
    int c  = wid >> 1;        // coord 0..3
    int n2 = wid & 1;         // N-half 0..1 (64 couts)
    int h = blockIdx.x, n = blockIdx.y;

    uint32_t acc[4][8][2];    // f16x2 accumulators [mtile][ntile]
#pragma unroll
    for (int a = 0; a < 4; a++)
#pragma unroll
        for (int b = 0; b < 8; b++) { acc[a][b][0] = 0u; acc[a][b][1] = 0u; }

    // Double-buffered B fragments (per kt). Preload chunk 0, kt 0.
    uint2 bfr[2][8];
#pragma unroll
    for (int nt = 0; nt < 8; nt++)
        bfr[0][nt] = g_wfrag[(((size_t)(c * 12 + 0) * 4 + 0) * 16 + n2 * 8 + nt) * 32 + lane];

    // Prologue: raw0+raw1 in flight; transform chunk 0 fully.
    issue_raw(smem, tid, n, h, 0);
    issue_raw(smem, tid, n, h, 1);
    asm volatile("cp.async.wait_group 1;\n");   // raw0 complete
    __syncthreads();
#pragma unroll
    for (int p = 0; p < 8; p++) transform_p(smem, tid, 0, p);

    int rl  = lane & 15;
    int cl2 = (lane >> 4) * 8;

    for (int s = 0; s < 12; s++) {
        // wait raw(s+1) -> transform(s+1) may read it; barrier publishes
        // transform(s) (V[s&1]) to all warps.
        asm volatile("cp.async.wait_group 0;\n");
        __syncthreads();

        // Slot s&1 held raw(s), consumed by transform(s) last chunk -> reuse.
        if (s + 2 < 12) issue_raw(smem, tid, n, h, s + 2);

        const char* sVc = smem + V_OFF + (s & 1) * VBUF_SZ + c * VCOORD_SZ;
#pragma unroll
        for (int kt = 0; kt < 4; kt++) {
            int cur = kt & 1, nxt = cur ^ 1;
            // Prefetch next kt's B (or next chunk's kt0) into the other buffer.
            if (!(s == 11 && kt == 3)) {
                int s2  = (kt < 3) ? s : s + 1;
                int kt2 = (kt < 3) ? kt + 1 : 0;
                const uint2* gBn = g_wfrag
                    + (((size_t)(c * 12 + s2) * 4 + kt2) * 16 + n2 * 8) * 32 + lane;
#pragma unroll
                for (int nt = 0; nt < 8; nt++)
                    bfr[nxt][nt] = gBn[nt * 32];
            }

            uint32_t a[4][4];
#pragma unroll
            for (int mt = 0; mt < 4; mt++) {
                uint32_t addr = (uint32_t)__cvta_generic_to_shared(
                    sVc + ((mt * 16 + rl) * A_PAD + kt * 16 + cl2) * 2);
                asm volatile(
                    "ldmatrix.sync.aligned.m8n8.x4.shared.b16 {%0,%1,%2,%3}, [%4];"
                    : "=r"(a[mt][0]), "=r"(a[mt][1]), "=r"(a[mt][2]), "=r"(a[mt][3])
                    : "r"(addr));
            }
#pragma unroll
            for (int mt = 0; mt < 4; mt++)
#pragma unroll
                for (int nt = 0; nt < 8; nt++)
                    asm volatile(
                        "mma.sync.aligned.m16n8k16.row.col.f16.f16.f16.f16 "
                        "{%0,%1}, {%2,%3,%4,%5}, {%6,%7}, {%0,%1};"
                        : "+r"(acc[mt][nt][0]), "+r"(acc[mt][nt][1])
                        : "r"(a[mt][0]), "r"(a[mt][1]), "r"(a[mt][2]), "r"(a[mt][3]),
                          "r"(bfr[cur][nt].x), "r"(bfr[cur][nt].y));

            // Two transform parts for chunk s+1 (writes V[(s+1)&1], disjoint
            // from this chunk's V[s&1] reads -> drains under the MMA stream).
            if (s < 11) {
                transform_p(smem, tid, s + 1, 2 * kt);
                transform_p(smem, tid, s + 1, 2 * kt + 1);
            }
        }
    }

    // ---- Epilogue: inverse transform y0=M0+M1+M2, y1=M1-M2-M3, * alpha[w] ----
    __syncthreads();
    __half* Vr = (__half*)(smem + V_OFF);    // [coord4][tile64][co 132-pad]
#pragma unroll
    for (int mt = 0; mt < 4; mt++) {
        int r1 = mt * 16 + (lane >> 2);      // tile index
#pragma unroll
        for (int nt = 0; nt < 8; nt++) {
            int co0 = n2 * 64 + nt * 8 + (lane & 3) * 2;
            *(uint32_t*)&Vr[((size_t)(c * 64 + r1) * 132) + co0]     = acc[mt][nt][0];
            *(uint32_t*)&Vr[((size_t)(c * 64 + r1 + 8) * 132) + co0] = acc[mt][nt][1];
        }
    }
    __syncthreads();

    float al[4];
#pragma unroll
    for (int k = 0; k < 4; k++) al[k] = g_alpha[lane + k * 32];

#pragma unroll
    for (int q = 0; q < 16; q++) {
        int co = wid * 16 + q;
        float* ob = out + (((size_t)n * C_OUT + co) * HW + h) * HW;
#pragma unroll
        for (int k = 0; k < 4; k++) {
            int w = lane + k * 32;
            int t = w >> 1, p = w & 1;
            float m0 = __half2float(Vr[(size_t)(0 * 64 + t) * 132 + co]);
            float m1 = __half2float(Vr[(size_t)(1 * 64 + t) * 132 + co]);
            float m2 = __half2float(Vr[(size_t)(2 * 64 + t) * 132 + co]);
            float m3 = __half2float(Vr[(size_t)(3 * 64 + t) * 132 + co]);
            float y = p ? (m1 - m2 - m3) : (m0 + m1 + m2);
            __stcs(&ob[w], y * al[k]);       // streaming: out never re-read
        }
    }
}

// ---------------------------------------------------------------------------
extern "C" void kernel_launch(void* const* d_in, const int* in_sizes, int n_in,
                              void* d_out, int out_size) {
    (void)in_sizes; (void)n_in; (void)out_size;
    const float* x = (const float*)d_in[0];
    const float* w = (const float*)d_in[1];
    float* out = (float*)d_out;

    cudaFuncSetAttribute(conv_kernel,
                         cudaFuncAttributeMaxDynamicSharedMemorySize, SMEM_DYN);

    dim3 pg(4, 4, N_IMG * HW);
    dim3 pb(32, 8);
    pack_x_kernel<<<pg, pb>>>(x);
    pack_w_alpha_kernel<<<512, 256>>>(w);
    conv_kernel<<<dim3(HW, N_IMG), 256, SMEM_DYN>>>(out);
}